// round 14
// baseline (speedup 1.0000x reference)
#include <cuda_runtime.h>
#include <cuda_bf16.h>
#include <cstdint>

#define NN 10240
#define EE 160000

// Scratch (static device globals)
__device__ __nv_bfloat16 g_G[(size_t)NN * 4096];   // G[n][kb][o][ki]: kb=k/8 (16), o (32), ki=k%8 (8)
__device__ float g_hb[NN * 32];
__device__ float g_Bperm[4096 * 32];
__device__ float g_sum_ef[NN * 32];
__device__ float g_sum_tr[NN * 3];
__device__ int   g_cnt[NN];        // row-degree (mean)
__device__ int   g_deg[NN];        // col-degree (sort)
__device__ int   g_cur[NN];
// sorted edge data (by col)
__device__ int   g_srow[EE];
__device__ int   g_scol[EE];
__device__ float g_sea[(size_t)EE * 8];
__device__ float g_scd[(size_t)EE * 4];

// ---------------- zero ----------------
__global__ void zero_kernel(int N) {
    int i = blockIdx.x * blockDim.x + threadIdx.x;
    if (i < N * 32) g_sum_ef[i] = 0.f;
    if (i < N * 3)  g_sum_tr[i] = 0.f;
    if (i < N) { g_cnt[i] = 0; g_deg[i] = 0; }
}

// ---------------- permute Wk2 for the [kb][o][ki] G layout ----------------
__global__ void bperm_kernel(const float* __restrict__ Wk2) {
    int idx = blockIdx.x * blockDim.x + threadIdx.x;
    if (idx >= 4096 * 32) return;
    int i = idx & 31;
    int c = idx >> 5;
    int kb = c >> 8;
    int o  = (c >> 3) & 31;
    int ki = c & 7;
    int k  = kb * 8 + ki;
    g_Bperm[idx] = Wk2[k * 1024 + i * 32 + o];
}

// ---------------- hb = h @ bk2 ----------------
__global__ void hb_kernel(const float* __restrict__ h, const float* __restrict__ bk2, int N) {
    int warp = threadIdx.x >> 5, lane = threadIdx.x & 31;
    int n = blockIdx.x * 8 + warp;
    if (n >= N) return;
    float hv = h[n * 32 + lane];
    float acc = 0.f;
#pragma unroll
    for (int i = 0; i < 32; i++)
        acc = fmaf(__shfl_sync(0xffffffffu, hv, i), bk2[i * 32 + lane], acc);
    g_hb[n * 32 + lane] = acc;
}

// ---------------- G = H @ Bperm, bf16, 2 cols/thread, 4 accumulator chains ----------------
__global__ __launch_bounds__(256) void g_kernel(const float* __restrict__ h, int N) {
    __shared__ float hs[64 * 32];
    int n0 = blockIdx.x * 64;
    int c0 = (blockIdx.y * 256 + threadIdx.x) * 2;
    int lim = N * 32;
    for (int t = threadIdx.x; t < 64 * 32; t += 256) {
        int gi = n0 * 32 + t;
        hs[t] = (gi < lim) ? h[gi] : 0.f;
    }
    __syncthreads();
    float b0[32], b1[32];
#pragma unroll
    for (int q = 0; q < 8; q++) {
        float4 v0 = *reinterpret_cast<const float4*>(&g_Bperm[(size_t)c0 * 32 + q * 4]);
        float4 v1 = *reinterpret_cast<const float4*>(&g_Bperm[(size_t)(c0 + 1) * 32 + q * 4]);
        b0[q*4+0] = v0.x; b0[q*4+1] = v0.y; b0[q*4+2] = v0.z; b0[q*4+3] = v0.w;
        b1[q*4+0] = v1.x; b1[q*4+1] = v1.y; b1[q*4+2] = v1.z; b1[q*4+3] = v1.w;
    }
    int nmax = min(64, N - n0);
    for (int nn = 0; nn < nmax; nn++) {
        float a0 = 0.f, a1 = 0.f, a2 = 0.f, a3 = 0.f;   // even/odd chunk split
#pragma unroll
        for (int q = 0; q < 8; q += 2) {
            float4 hv = *reinterpret_cast<const float4*>(&hs[nn * 32 + q * 4]);
            float4 hw = *reinterpret_cast<const float4*>(&hs[nn * 32 + (q + 1) * 4]);
            a0 = fmaf(hv.x, b0[q*4+0], a0); a1 = fmaf(hv.x, b1[q*4+0], a1);
            a2 = fmaf(hw.x, b0[q*4+4], a2); a3 = fmaf(hw.x, b1[q*4+4], a3);
            a0 = fmaf(hv.y, b0[q*4+1], a0); a1 = fmaf(hv.y, b1[q*4+1], a1);
            a2 = fmaf(hw.y, b0[q*4+5], a2); a3 = fmaf(hw.y, b1[q*4+5], a3);
            a0 = fmaf(hv.z, b0[q*4+2], a0); a1 = fmaf(hv.z, b1[q*4+2], a1);
            a2 = fmaf(hw.z, b0[q*4+6], a2); a3 = fmaf(hw.z, b1[q*4+6], a3);
            a0 = fmaf(hv.w, b0[q*4+3], a0); a1 = fmaf(hv.w, b1[q*4+3], a1);
            a2 = fmaf(hw.w, b0[q*4+7], a2); a3 = fmaf(hw.w, b1[q*4+7], a3);
        }
        *reinterpret_cast<__nv_bfloat162*>(&g_G[(size_t)(n0 + nn) * 4096 + c0]) =
            __floats2bfloat162_rn(a0 + a2, a1 + a3);
    }
}

// ---------------- histograms ----------------
__global__ void hist_kernel(const int* __restrict__ ei, int E) {
    int e = blockIdx.x * blockDim.x + threadIdx.x;
    if (e >= E) return;
    atomicAdd(&g_deg[ei[E + e]], 1);
    atomicAdd(&g_cnt[ei[e]], 1);
}

// ---------------- exclusive scan of col-degrees ----------------
__global__ void scan_kernel(int N) {
    __shared__ int s[1024];
    int tid = threadIdx.x;
    int base = tid * 10;
    int local[10];
    int sum = 0;
#pragma unroll
    for (int i = 0; i < 10; i++) {
        int idx = base + i;
        int v = (idx < N) ? g_deg[idx] : 0;
        local[i] = sum; sum += v;
    }
    s[tid] = sum;
    __syncthreads();
    for (int off = 1; off < 1024; off <<= 1) {
        int v = (tid >= off) ? s[tid - off] : 0;
        __syncthreads();
        s[tid] += v;
        __syncthreads();
    }
    int pre = (tid > 0) ? s[tid - 1] : 0;
#pragma unroll
    for (int i = 0; i < 10; i++) {
        int idx = base + i;
        if (idx < N) g_cur[idx] = pre + local[i];
    }
}

// ---------------- scatter: build fully sorted edge records ----------------
__global__ void scatter_kernel(const int* __restrict__ ei, const float* __restrict__ ea,
                               const float* __restrict__ coord, int E) {
    int e = blockIdx.x * blockDim.x + threadIdx.x;
    if (e >= E) return;
    int row = ei[e];
    int col = ei[E + e];
    int pos = atomicAdd(&g_cur[col], 1);
    g_srow[pos] = row;
    g_scol[pos] = col;
    float a0 = ea[e * 6 + 0], a1 = ea[e * 6 + 1], a2 = ea[e * 6 + 2];
    float a3 = ea[e * 6 + 3], a4 = ea[e * 6 + 4], a5 = ea[e * 6 + 5];
    float4* sp = reinterpret_cast<float4*>(&g_sea[(size_t)pos * 8]);
    sp[0] = make_float4(a0, a1, a2, a3);
    sp[1] = make_float4(a4, a5, 0.f, 0.f);
    float c0 = coord[row * 3 + 0] - coord[col * 3 + 0];
    float c1 = coord[row * 3 + 1] - coord[col * 3 + 1];
    float c2 = coord[row * 3 + 2] - coord[col * 3 + 2];
    *reinterpret_cast<float4*>(&g_scd[(size_t)pos * 4]) = make_float4(c0, c1, c2, 0.f);
}

// ---------------- pair gather with dedup (R13 proven inner loops) ----------------
__device__ __forceinline__ void gather_pair(
        int colA, int colB, int lane,
        const float* __restrict__ rzA, const float* __restrict__ rzB,
        float& accA, float& accB) {
    const __nv_bfloat16* gpA = g_G + (size_t)colA * 4096 + lane * 8;
    accA = g_hb[colA * 32 + lane];
    if (colB == colA) {
        accB = accA;
#pragma unroll
        for (int kc = 0; kc < 16; kc++) {
            uint4 gv = *reinterpret_cast<const uint4*>(gpA + kc * 256);
            float4 ra0 = *reinterpret_cast<const float4*>(&rzA[kc * 8]);
            float4 rb0 = *reinterpret_cast<const float4*>(&rzA[kc * 8 + 4]);
            float4 ra1 = *reinterpret_cast<const float4*>(&rzB[kc * 8]);
            float4 rb1 = *reinterpret_cast<const float4*>(&rzB[kc * 8 + 4]);
            float2 f0 = __bfloat1622float2(*reinterpret_cast<const __nv_bfloat162*>(&gv.x));
            float2 f1 = __bfloat1622float2(*reinterpret_cast<const __nv_bfloat162*>(&gv.y));
            float2 f2 = __bfloat1622float2(*reinterpret_cast<const __nv_bfloat162*>(&gv.z));
            float2 f3 = __bfloat1622float2(*reinterpret_cast<const __nv_bfloat162*>(&gv.w));
            accA = fmaf(ra0.x, f0.x, accA); accB = fmaf(ra1.x, f0.x, accB);
            accA = fmaf(ra0.y, f0.y, accA); accB = fmaf(ra1.y, f0.y, accB);
            accA = fmaf(ra0.z, f1.x, accA); accB = fmaf(ra1.z, f1.x, accB);
            accA = fmaf(ra0.w, f1.y, accA); accB = fmaf(ra1.w, f1.y, accB);
            accA = fmaf(rb0.x, f2.x, accA); accB = fmaf(rb1.x, f2.x, accB);
            accA = fmaf(rb0.y, f2.y, accA); accB = fmaf(rb1.y, f2.y, accB);
            accA = fmaf(rb0.z, f3.x, accA); accB = fmaf(rb1.z, f3.x, accB);
            accA = fmaf(rb0.w, f3.y, accA); accB = fmaf(rb1.w, f3.y, accB);
        }
    } else {
        const __nv_bfloat16* gpB = g_G + (size_t)colB * 4096 + lane * 8;
        accB = g_hb[colB * 32 + lane];
#pragma unroll
        for (int kc = 0; kc < 16; kc++) {
            uint4 gv0 = *reinterpret_cast<const uint4*>(gpA + kc * 256);
            uint4 gv1 = *reinterpret_cast<const uint4*>(gpB + kc * 256);
            float4 ra0 = *reinterpret_cast<const float4*>(&rzA[kc * 8]);
            float4 rb0 = *reinterpret_cast<const float4*>(&rzA[kc * 8 + 4]);
            float4 ra1 = *reinterpret_cast<const float4*>(&rzB[kc * 8]);
            float4 rb1 = *reinterpret_cast<const float4*>(&rzB[kc * 8 + 4]);
            float2 f;
            f = __bfloat1622float2(*reinterpret_cast<const __nv_bfloat162*>(&gv0.x));
            accA = fmaf(ra0.x, f.x, accA); accA = fmaf(ra0.y, f.y, accA);
            f = __bfloat1622float2(*reinterpret_cast<const __nv_bfloat162*>(&gv0.y));
            accA = fmaf(ra0.z, f.x, accA); accA = fmaf(ra0.w, f.y, accA);
            f = __bfloat1622float2(*reinterpret_cast<const __nv_bfloat162*>(&gv0.z));
            accA = fmaf(rb0.x, f.x, accA); accA = fmaf(rb0.y, f.y, accA);
            f = __bfloat1622float2(*reinterpret_cast<const __nv_bfloat162*>(&gv0.w));
            accA = fmaf(rb0.z, f.x, accA); accA = fmaf(rb0.w, f.y, accA);
            f = __bfloat1622float2(*reinterpret_cast<const __nv_bfloat162*>(&gv1.x));
            accB = fmaf(ra1.x, f.x, accB); accB = fmaf(ra1.y, f.y, accB);
            f = __bfloat1622float2(*reinterpret_cast<const __nv_bfloat162*>(&gv1.y));
            accB = fmaf(ra1.z, f.x, accB); accB = fmaf(ra1.w, f.y, accB);
            f = __bfloat1622float2(*reinterpret_cast<const __nv_bfloat162*>(&gv1.z));
            accB = fmaf(rb1.x, f.x, accB); accB = fmaf(rb1.y, f.y, accB);
            f = __bfloat1622float2(*reinterpret_cast<const __nv_bfloat162*>(&gv1.w));
            accB = fmaf(rb1.z, f.x, accB); accB = fmaf(rb1.w, f.y, accB);
        }
    }
}

// ---------------- edge kernel: 4 edges/warp-iter, col-dedup gather ----------------
__global__ __launch_bounds__(256) void edge_kernel(
        const float* __restrict__ Wk1, const float* __restrict__ bk1,
        const float* __restrict__ Wc1, const float* __restrict__ bc1,
        const float* __restrict__ Wc2, int E) {
    __shared__ float sWk1[768], sbk1[128], sbc1[64], sWc2[64];
    __shared__ float2 sWc1p[1024];
    __shared__ float s_rz[8][4][128];
    __shared__ __align__(16) float s_ef[8][4][32];
    int tid = threadIdx.x;
    for (int t = tid; t < 768; t += 256)  sWk1[t] = Wk1[t];
    for (int t = tid; t < 1024; t += 256) {
        int o = t >> 5, l = t & 31;
        sWc1p[t] = make_float2(Wc1[o * 64 + l], Wc1[o * 64 + 32 + l]);
    }
    if (tid < 128) sbk1[tid] = bk1[tid];
    if (tid < 64)  sbc1[tid] = bc1[tid];
    if (tid < 64)  sWc2[tid] = Wc2[tid];
    __syncthreads();

    int warp = tid >> 5, lane = tid & 31;
    const unsigned FULL = 0xffffffffu;
    int per = (E + gridDim.x - 1) / gridDim.x;
    int j0 = blockIdx.x * per;
    int j1 = min(j0 + per, E);

    for (int j = j0 + warp * 4; j < j1; j += 32) {
        int jj[4], row[4], col[4];
        bool val[4];
#pragma unroll
        for (int i = 0; i < 4; i++) {
            int x = j + i;
            val[i] = x < j1;
            jj[i] = val[i] ? x : (j1 - 1);
            row[i] = g_srow[jj[i]];
            col[i] = g_scol[jj[i]];
        }

        // rz MLP in two passes of 2 edges (caps live ea registers)
#pragma unroll
        for (int p = 0; p < 2; p++) {
            int iA = 2 * p, iB = 2 * p + 1;
            float eaA = (lane < 6) ? g_sea[(size_t)jj[iA] * 8 + lane] : 0.f;
            float eaB = (lane < 6) ? g_sea[(size_t)jj[iB] * 8 + lane] : 0.f;
            float a0A = __shfl_sync(FULL, eaA, 0), a1A = __shfl_sync(FULL, eaA, 1);
            float a2A = __shfl_sync(FULL, eaA, 2), a3A = __shfl_sync(FULL, eaA, 3);
            float a4A = __shfl_sync(FULL, eaA, 4), a5A = __shfl_sync(FULL, eaA, 5);
            float a0B = __shfl_sync(FULL, eaB, 0), a1B = __shfl_sync(FULL, eaB, 1);
            float a2B = __shfl_sync(FULL, eaB, 2), a3B = __shfl_sync(FULL, eaB, 3);
            float a4B = __shfl_sync(FULL, eaB, 4), a5B = __shfl_sync(FULL, eaB, 5);
#pragma unroll
            for (int r = 0; r < 4; r++) {
                int k = r * 32 + lane;
                float w0 = sWk1[k], w1 = sWk1[128 + k], w2 = sWk1[256 + k];
                float w3 = sWk1[384 + k], w4 = sWk1[512 + k], w5 = sWk1[640 + k];
                float b = sbk1[k];
                float vA = b, vBv = b;
                vA = fmaf(a0A, w0, vA); vBv = fmaf(a0B, w0, vBv);
                vA = fmaf(a1A, w1, vA); vBv = fmaf(a1B, w1, vBv);
                vA = fmaf(a2A, w2, vA); vBv = fmaf(a2B, w2, vBv);
                vA = fmaf(a3A, w3, vA); vBv = fmaf(a3B, w3, vBv);
                vA = fmaf(a4A, w4, vA); vBv = fmaf(a4B, w4, vBv);
                vA = fmaf(a5A, w5, vA); vBv = fmaf(a5B, w5, vBv);
                s_rz[warp][iA][k] = fmaxf(vA, 0.f);
                s_rz[warp][iB][k] = fmaxf(vBv, 0.f);
            }
        }
        __syncwarp();

        // gather: all-4 dedup fast path (sorted => col0==col3 implies all equal)
        float acc[4];
        if (col[3] == col[0]) {
            const __nv_bfloat16* gp = g_G + (size_t)col[0] * 4096 + lane * 8;
            float hbv = g_hb[col[0] * 32 + lane];
            acc[0] = hbv; acc[1] = hbv; acc[2] = hbv; acc[3] = hbv;
#pragma unroll
            for (int kc = 0; kc < 16; kc++) {
                uint4 gv = *reinterpret_cast<const uint4*>(gp + kc * 256);
                float2 f0 = __bfloat1622float2(*reinterpret_cast<const __nv_bfloat162*>(&gv.x));
                float2 f1 = __bfloat1622float2(*reinterpret_cast<const __nv_bfloat162*>(&gv.y));
                float2 f2 = __bfloat1622float2(*reinterpret_cast<const __nv_bfloat162*>(&gv.z));
                float2 f3 = __bfloat1622float2(*reinterpret_cast<const __nv_bfloat162*>(&gv.w));
#pragma unroll
                for (int e = 0; e < 4; e++) {
                    float4 ra = *reinterpret_cast<const float4*>(&s_rz[warp][e][kc * 8]);
                    float4 rb = *reinterpret_cast<const float4*>(&s_rz[warp][e][kc * 8 + 4]);
                    float a = acc[e];
                    a = fmaf(ra.x, f0.x, a); a = fmaf(ra.y, f0.y, a);
                    a = fmaf(ra.z, f1.x, a); a = fmaf(ra.w, f1.y, a);
                    a = fmaf(rb.x, f2.x, a); a = fmaf(rb.y, f2.y, a);
                    a = fmaf(rb.z, f3.x, a); a = fmaf(rb.w, f3.y, a);
                    acc[e] = a;
                }
            }
        } else {
            gather_pair(col[0], col[1], lane, s_rz[warp][0], s_rz[warp][1], acc[0], acc[1]);
            gather_pair(col[2], col[3], lane, s_rz[warp][2], s_rz[warp][3], acc[2], acc[3]);
        }

        // stash ef; coord MLP with 4-way shared weight LDS
#pragma unroll
        for (int e = 0; e < 4; e++) s_ef[warp][e][lane] = acc[e];
        __syncwarp();

        float t0[4], t1[4];
#pragma unroll
        for (int e = 0; e < 4; e++) { t0[e] = sbc1[lane]; t1[e] = sbc1[32 + lane]; }
#pragma unroll
        for (int q = 0; q < 8; q++) {
            float2 w0 = sWc1p[(q * 4 + 0) * 32 + lane];
            float2 w1 = sWc1p[(q * 4 + 1) * 32 + lane];
            float2 w2 = sWc1p[(q * 4 + 2) * 32 + lane];
            float2 w3 = sWc1p[(q * 4 + 3) * 32 + lane];
#pragma unroll
            for (int e = 0; e < 4; e++) {
                float4 ef = *reinterpret_cast<const float4*>(&s_ef[warp][e][q * 4]);
                t0[e] = fmaf(ef.x, w0.x, t0[e]); t1[e] = fmaf(ef.x, w0.y, t1[e]);
                t0[e] = fmaf(ef.y, w1.x, t0[e]); t1[e] = fmaf(ef.y, w1.y, t1[e]);
                t0[e] = fmaf(ef.z, w2.x, t0[e]); t1[e] = fmaf(ef.z, w2.y, t1[e]);
                t0[e] = fmaf(ef.w, w3.x, t0[e]); t1[e] = fmaf(ef.w, w3.y, t1[e]);
            }
        }
        float wc2a = sWc2[lane], wc2b = sWc2[32 + lane];
        float p4[4];
#pragma unroll
        for (int e = 0; e < 4; e++) {
            float u0 = fmaxf(t0[e], 0.f), u1 = fmaxf(t1[e], 0.f);
            p4[e] = fmaf(u0, wc2a, u1 * wc2b);
        }
#pragma unroll
        for (int off = 16; off; off >>= 1) {
            p4[0] += __shfl_xor_sync(FULL, p4[0], off);
            p4[1] += __shfl_xor_sync(FULL, p4[1], off);
            p4[2] += __shfl_xor_sync(FULL, p4[2], off);
            p4[3] += __shfl_xor_sync(FULL, p4[3], off);
        }

#pragma unroll
        for (int e = 0; e < 4; e++) {
            if (val[e]) {
                atomicAdd(&g_sum_ef[row[e] * 32 + lane], acc[e]);
                if (lane < 3) {
                    float cd = g_scd[(size_t)jj[e] * 4 + lane];
                    atomicAdd(&g_sum_tr[row[e] * 3 + lane], cd * p4[e]);
                }
            }
        }
        __syncwarp();
    }
}

// ---------------- node epilogue ----------------
__global__ void node_kernel(const float* __restrict__ h, const float* __restrict__ coord,
                            const float* __restrict__ root, const float* __restrict__ bias,
                            float* __restrict__ out, int N) {
    int warp = threadIdx.x >> 5, lane = threadIdx.x & 31;
    int n = blockIdx.x * 8 + warp;
    if (n >= N) return;
    float hv = h[n * 32 + lane];
    float inv = 1.f / fmaxf((float)g_cnt[n], 1.f);
    float agg = g_sum_ef[n * 32 + lane] * inv + bias[lane];
#pragma unroll
    for (int i = 0; i < 32; i++)
        agg = fmaf(__shfl_sync(0xffffffffu, hv, i), root[i * 32 + lane], agg);
    out[n * 32 + lane] = hv + fmaxf(agg, 0.f) * 0.25f;
    if (lane < 3)
        out[N * 32 + n * 3 + lane] = g_sum_tr[n * 3 + lane] * inv * 0.25f + coord[n * 3 + lane];
}

extern "C" void kernel_launch(void* const* d_in, const int* in_sizes, int n_in,
                              void* d_out, int out_size) {
    const float* h     = (const float*)d_in[0];
    const int*   ei    = (const int*)  d_in[1];
    const float* coord = (const float*)d_in[2];
    const float* ea    = (const float*)d_in[3];
    const float* Wk1   = (const float*)d_in[4];
    const float* bk1   = (const float*)d_in[5];
    const float* Wk2   = (const float*)d_in[6];
    const float* bk2   = (const float*)d_in[7];
    const float* root  = (const float*)d_in[8];
    const float* bias  = (const float*)d_in[9];
    const float* Wc1   = (const float*)d_in[10];
    const float* bc1   = (const float*)d_in[11];
    const float* Wc2   = (const float*)d_in[12];

    int N = in_sizes[0] / 32;
    int E = in_sizes[1] / 2;
    float* out = (float*)d_out;

    zero_kernel<<<(N * 32 + 255) / 256, 256>>>(N);
    bperm_kernel<<<(4096 * 32 + 255) / 256, 256>>>(Wk2);
    hb_kernel<<<(N + 7) / 8, 256>>>(h, bk2, N);
    dim3 gg((N + 63) / 64, 8);
    g_kernel<<<gg, 256>>>(h, N);
    hist_kernel<<<(E + 255) / 256, 256>>>(ei, E);
    scan_kernel<<<1, 1024>>>(N);
    scatter_kernel<<<(E + 255) / 256, 256>>>(ei, ea, coord, E);
    edge_kernel<<<592, 256>>>(Wk1, bk1, Wc1, bc1, Wc2, E);
    node_kernel<<<(N + 7) / 8, 256>>>(h, coord, root, bias, out, N);
}

// round 16
// speedup vs baseline: 1.1392x; 1.1392x over previous
#include <cuda_runtime.h>
#include <cuda_bf16.h>
#include <cstdint>

#define NN 10240
#define EE 160000

// Scratch (static device globals)
__device__ __nv_bfloat16 g_G[(size_t)NN * 4096];   // G[n][kb][o][ki]: kb=k/8 (16), o (32), ki=k%8 (8)
__device__ float g_hb[NN * 32];
__device__ float g_Bperm[4096 * 32];
__device__ float g_sum_ef[NN * 32];
__device__ float g_sum_tr[NN * 3];
__device__ int   g_cnt[NN];        // row-degree (mean)
__device__ int   g_deg[NN];        // col-degree (sort)
__device__ int   g_cur[NN];
// sorted edge data (by col)
__device__ int   g_srow[EE];
__device__ int   g_scol[EE];
__device__ float g_sea[(size_t)EE * 8];
__device__ float g_scd[(size_t)EE * 4];

// ---------------- zero (degree arrays only; sums zeroed in hb_kernel) ----------------
__global__ void zero_kernel(int N) {
    int i = blockIdx.x * blockDim.x + threadIdx.x;
    if (i < N) { g_cnt[i] = 0; g_deg[i] = 0; }
}

// ---------------- permute Wk2 for the [kb][o][ki] G layout ----------------
__global__ void bperm_kernel(const float* __restrict__ Wk2) {
    int idx = blockIdx.x * blockDim.x + threadIdx.x;
    if (idx >= 4096 * 32) return;
    int i = idx & 31;
    int c = idx >> 5;
    int kb = c >> 8;
    int o  = (c >> 3) & 31;
    int ki = c & 7;
    int k  = kb * 8 + ki;
    g_Bperm[idx] = Wk2[k * 1024 + i * 32 + o];
}

// ---------------- hb = h @ bk2 ; also zeroes the edge accumulators ----------------
__global__ void hb_kernel(const float* __restrict__ h, const float* __restrict__ bk2, int N) {
    int warp = threadIdx.x >> 5, lane = threadIdx.x & 31;
    int n = blockIdx.x * 8 + warp;
    if (n >= N) return;
    float hv = h[n * 32 + lane];
    float acc = 0.f;
#pragma unroll
    for (int i = 0; i < 32; i++)
        acc = fmaf(__shfl_sync(0xffffffffu, hv, i), bk2[i * 32 + lane], acc);
    g_hb[n * 32 + lane] = acc;
    g_sum_ef[n * 32 + lane] = 0.f;
    if (lane < 3) g_sum_tr[n * 3 + lane] = 0.f;
}

// ---------------- G = H @ Bperm, bf16, 2 cols/thread (R5/R9/R13 proven) ----------------
__global__ __launch_bounds__(256) void g_kernel(const float* __restrict__ h, int N) {
    __shared__ float hs[64 * 32];
    int n0 = blockIdx.x * 64;
    int c0 = (blockIdx.y * 256 + threadIdx.x) * 2;
    int lim = N * 32;
    for (int t = threadIdx.x; t < 64 * 32; t += 256) {
        int gi = n0 * 32 + t;
        hs[t] = (gi < lim) ? h[gi] : 0.f;
    }
    __syncthreads();
    float b0[32], b1[32];
#pragma unroll
    for (int q = 0; q < 8; q++) {
        float4 v0 = *reinterpret_cast<const float4*>(&g_Bperm[(size_t)c0 * 32 + q * 4]);
        float4 v1 = *reinterpret_cast<const float4*>(&g_Bperm[(size_t)(c0 + 1) * 32 + q * 4]);
        b0[q*4+0] = v0.x; b0[q*4+1] = v0.y; b0[q*4+2] = v0.z; b0[q*4+3] = v0.w;
        b1[q*4+0] = v1.x; b1[q*4+1] = v1.y; b1[q*4+2] = v1.z; b1[q*4+3] = v1.w;
    }
    int nmax = min(64, N - n0);
    for (int nn = 0; nn < nmax; nn++) {
        float a0 = 0.f, a1 = 0.f;
#pragma unroll
        for (int q = 0; q < 8; q++) {
            float4 hv = *reinterpret_cast<const float4*>(&hs[nn * 32 + q * 4]);
            a0 = fmaf(hv.x, b0[q*4+0], a0); a1 = fmaf(hv.x, b1[q*4+0], a1);
            a0 = fmaf(hv.y, b0[q*4+1], a0); a1 = fmaf(hv.y, b1[q*4+1], a1);
            a0 = fmaf(hv.z, b0[q*4+2], a0); a1 = fmaf(hv.z, b1[q*4+2], a1);
            a0 = fmaf(hv.w, b0[q*4+3], a0); a1 = fmaf(hv.w, b1[q*4+3], a1);
        }
        *reinterpret_cast<__nv_bfloat162*>(&g_G[(size_t)(n0 + nn) * 4096 + c0]) =
            __floats2bfloat162_rn(a0, a1);
    }
}

// ---------------- histograms ----------------
__global__ void hist_kernel(const int* __restrict__ ei, int E) {
    int e = blockIdx.x * blockDim.x + threadIdx.x;
    if (e >= E) return;
    atomicAdd(&g_deg[ei[E + e]], 1);
    atomicAdd(&g_cnt[ei[e]], 1);
}

// ---------------- exclusive scan of col-degrees ----------------
__global__ void scan_kernel(int N) {
    __shared__ int s[1024];
    int tid = threadIdx.x;
    int base = tid * 10;
    int local[10];
    int sum = 0;
#pragma unroll
    for (int i = 0; i < 10; i++) {
        int idx = base + i;
        int v = (idx < N) ? g_deg[idx] : 0;
        local[i] = sum; sum += v;
    }
    s[tid] = sum;
    __syncthreads();
    for (int off = 1; off < 1024; off <<= 1) {
        int v = (tid >= off) ? s[tid - off] : 0;
        __syncthreads();
        s[tid] += v;
        __syncthreads();
    }
    int pre = (tid > 0) ? s[tid - 1] : 0;
#pragma unroll
    for (int i = 0; i < 10; i++) {
        int idx = base + i;
        if (idx < N) g_cur[idx] = pre + local[i];
    }
}

// ---------------- scatter: build fully sorted edge records ----------------
__global__ void scatter_kernel(const int* __restrict__ ei, const float* __restrict__ ea,
                               const float* __restrict__ coord, int E) {
    int e = blockIdx.x * blockDim.x + threadIdx.x;
    if (e >= E) return;
    int row = ei[e];
    int col = ei[E + e];
    int pos = atomicAdd(&g_cur[col], 1);
    g_srow[pos] = row;
    g_scol[pos] = col;
    float a0 = ea[e * 6 + 0], a1 = ea[e * 6 + 1], a2 = ea[e * 6 + 2];
    float a3 = ea[e * 6 + 3], a4 = ea[e * 6 + 4], a5 = ea[e * 6 + 5];
    float4* sp = reinterpret_cast<float4*>(&g_sea[(size_t)pos * 8]);
    sp[0] = make_float4(a0, a1, a2, a3);
    sp[1] = make_float4(a4, a5, 0.f, 0.f);
    float c0 = coord[row * 3 + 0] - coord[col * 3 + 0];
    float c1 = coord[row * 3 + 1] - coord[col * 3 + 1];
    float c2 = coord[row * 3 + 2] - coord[col * 3 + 2];
    *reinterpret_cast<float4*>(&g_scd[(size_t)pos * 4]) = make_float4(c0, c1, c2, 0.f);
}

// ---------------- edge kernel: 2 edges/warp-iter, col-dedup gather, 3 blocks/SM ----------------
__global__ __launch_bounds__(256, 3) void edge_kernel(
        const float* __restrict__ Wk1, const float* __restrict__ bk1,
        const float* __restrict__ Wc1, const float* __restrict__ bc1,
        const float* __restrict__ Wc2, int E) {
    __shared__ float sWk1[768], sbk1[128], sbc1[64], sWc2[64];
    __shared__ float2 sWc1p[1024];
    __shared__ float s_rz[8][2][128];
    __shared__ __align__(16) float s_ef[8][2][32];
    int tid = threadIdx.x;
    for (int t = tid; t < 768; t += 256)  sWk1[t] = Wk1[t];
    for (int t = tid; t < 1024; t += 256) {
        int o = t >> 5, l = t & 31;
        sWc1p[t] = make_float2(Wc1[o * 64 + l], Wc1[o * 64 + 32 + l]);
    }
    if (tid < 128) sbk1[tid] = bk1[tid];
    if (tid < 64)  sbc1[tid] = bc1[tid];
    if (tid < 64)  sWc2[tid] = Wc2[tid];
    __syncthreads();

    int warp = tid >> 5, lane = tid & 31;
    const unsigned FULL = 0xffffffffu;
    int per = (E + gridDim.x - 1) / gridDim.x;
    int j0 = blockIdx.x * per;
    int j1 = min(j0 + per, E);

    for (int j = j0 + warp * 2; j < j1; j += 16) {
        int jA = j;
        int jB = j + 1;
        bool vB = jB < j1;
        int row0 = g_srow[jA], col0 = g_scol[jA];
        int row1 = vB ? g_srow[jB] : row0;
        int col1 = vB ? g_scol[jB] : col0;

        float eaA = (lane < 6) ? g_sea[(size_t)jA * 8 + lane] : 0.f;
        float eaB = (vB && lane < 6) ? g_sea[(size_t)jB * 8 + lane] : 0.f;
        float a0A = __shfl_sync(FULL, eaA, 0), a1A = __shfl_sync(FULL, eaA, 1);
        float a2A = __shfl_sync(FULL, eaA, 2), a3A = __shfl_sync(FULL, eaA, 3);
        float a4A = __shfl_sync(FULL, eaA, 4), a5A = __shfl_sync(FULL, eaA, 5);
        float a0B = __shfl_sync(FULL, eaB, 0), a1B = __shfl_sync(FULL, eaB, 1);
        float a2B = __shfl_sync(FULL, eaB, 2), a3B = __shfl_sync(FULL, eaB, 3);
        float a4B = __shfl_sync(FULL, eaB, 4), a5B = __shfl_sync(FULL, eaB, 5);

        // rz = relu(ea @ Wk1 + bk1) for both edges; weight LDS shared
#pragma unroll
        for (int r = 0; r < 4; r++) {
            int k = r * 32 + lane;
            float w0 = sWk1[k], w1 = sWk1[128 + k], w2 = sWk1[256 + k];
            float w3 = sWk1[384 + k], w4 = sWk1[512 + k], w5 = sWk1[640 + k];
            float b = sbk1[k];
            float vA = b, vBv = b;
            vA = fmaf(a0A, w0, vA); vBv = fmaf(a0B, w0, vBv);
            vA = fmaf(a1A, w1, vA); vBv = fmaf(a1B, w1, vBv);
            vA = fmaf(a2A, w2, vA); vBv = fmaf(a2B, w2, vBv);
            vA = fmaf(a3A, w3, vA); vBv = fmaf(a3B, w3, vBv);
            vA = fmaf(a4A, w4, vA); vBv = fmaf(a4B, w4, vBv);
            vA = fmaf(a5A, w5, vA); vBv = fmaf(a5B, w5, vBv);
            s_rz[warp][0][k] = fmaxf(vA, 0.f);
            s_rz[warp][1][k] = fmaxf(vBv, 0.f);
        }
        __syncwarp();

        // ef = hb[col] + rz . G[col]; sorted pairs share col ~94% -> dedup branch
        float acc0 = g_hb[col0 * 32 + lane];
        float acc1;
        const __nv_bfloat16* gp0 = g_G + (size_t)col0 * 4096 + lane * 8;
        if (col1 == col0) {
            acc1 = acc0;
#pragma unroll
            for (int kc = 0; kc < 16; kc++) {
                uint4 gv = *reinterpret_cast<const uint4*>(gp0 + kc * 256);
                float4 ra0 = *reinterpret_cast<const float4*>(&s_rz[warp][0][kc * 8]);
                float4 rb0 = *reinterpret_cast<const float4*>(&s_rz[warp][0][kc * 8 + 4]);
                float4 ra1 = *reinterpret_cast<const float4*>(&s_rz[warp][1][kc * 8]);
                float4 rb1 = *reinterpret_cast<const float4*>(&s_rz[warp][1][kc * 8 + 4]);
                float2 f0 = __bfloat1622float2(*reinterpret_cast<const __nv_bfloat162*>(&gv.x));
                float2 f1 = __bfloat1622float2(*reinterpret_cast<const __nv_bfloat162*>(&gv.y));
                float2 f2 = __bfloat1622float2(*reinterpret_cast<const __nv_bfloat162*>(&gv.z));
                float2 f3 = __bfloat1622float2(*reinterpret_cast<const __nv_bfloat162*>(&gv.w));
                acc0 = fmaf(ra0.x, f0.x, acc0); acc1 = fmaf(ra1.x, f0.x, acc1);
                acc0 = fmaf(ra0.y, f0.y, acc0); acc1 = fmaf(ra1.y, f0.y, acc1);
                acc0 = fmaf(ra0.z, f1.x, acc0); acc1 = fmaf(ra1.z, f1.x, acc1);
                acc0 = fmaf(ra0.w, f1.y, acc0); acc1 = fmaf(ra1.w, f1.y, acc1);
                acc0 = fmaf(rb0.x, f2.x, acc0); acc1 = fmaf(rb1.x, f2.x, acc1);
                acc0 = fmaf(rb0.y, f2.y, acc0); acc1 = fmaf(rb1.y, f2.y, acc1);
                acc0 = fmaf(rb0.z, f3.x, acc0); acc1 = fmaf(rb1.z, f3.x, acc1);
                acc0 = fmaf(rb0.w, f3.y, acc0); acc1 = fmaf(rb1.w, f3.y, acc1);
            }
        } else {
            const __nv_bfloat16* gp1 = g_G + (size_t)col1 * 4096 + lane * 8;
            acc1 = g_hb[col1 * 32 + lane];
#pragma unroll
            for (int kc = 0; kc < 16; kc++) {
                uint4 gv0 = *reinterpret_cast<const uint4*>(gp0 + kc * 256);
                uint4 gv1 = *reinterpret_cast<const uint4*>(gp1 + kc * 256);
                float4 ra0 = *reinterpret_cast<const float4*>(&s_rz[warp][0][kc * 8]);
                float4 rb0 = *reinterpret_cast<const float4*>(&s_rz[warp][0][kc * 8 + 4]);
                float4 ra1 = *reinterpret_cast<const float4*>(&s_rz[warp][1][kc * 8]);
                float4 rb1 = *reinterpret_cast<const float4*>(&s_rz[warp][1][kc * 8 + 4]);
                float2 f;
                f = __bfloat1622float2(*reinterpret_cast<const __nv_bfloat162*>(&gv0.x));
                acc0 = fmaf(ra0.x, f.x, acc0); acc0 = fmaf(ra0.y, f.y, acc0);
                f = __bfloat1622float2(*reinterpret_cast<const __nv_bfloat162*>(&gv0.y));
                acc0 = fmaf(ra0.z, f.x, acc0); acc0 = fmaf(ra0.w, f.y, acc0);
                f = __bfloat1622float2(*reinterpret_cast<const __nv_bfloat162*>(&gv0.z));
                acc0 = fmaf(rb0.x, f.x, acc0); acc0 = fmaf(rb0.y, f.y, acc0);
                f = __bfloat1622float2(*reinterpret_cast<const __nv_bfloat162*>(&gv0.w));
                acc0 = fmaf(rb0.z, f.x, acc0); acc0 = fmaf(rb0.w, f.y, acc0);
                f = __bfloat1622float2(*reinterpret_cast<const __nv_bfloat162*>(&gv1.x));
                acc1 = fmaf(ra1.x, f.x, acc1); acc1 = fmaf(ra1.y, f.y, acc1);
                f = __bfloat1622float2(*reinterpret_cast<const __nv_bfloat162*>(&gv1.y));
                acc1 = fmaf(ra1.z, f.x, acc1); acc1 = fmaf(ra1.w, f.y, acc1);
                f = __bfloat1622float2(*reinterpret_cast<const __nv_bfloat162*>(&gv1.z));
                acc1 = fmaf(rb1.x, f.x, acc1); acc1 = fmaf(rb1.y, f.y, acc1);
                f = __bfloat1622float2(*reinterpret_cast<const __nv_bfloat162*>(&gv1.w));
                acc1 = fmaf(rb1.z, f.x, acc1); acc1 = fmaf(rb1.w, f.y, acc1);
            }
        }

        // stash ef to smem; read back as float4 broadcasts for the coord MLP
        s_ef[warp][0][lane] = acc0;
        s_ef[warp][1][lane] = acc1;
        __syncwarp();

        float t0A = sbc1[lane], t1A = sbc1[32 + lane];
        float t0B = t0A, t1B = t1A;
#pragma unroll
        for (int q = 0; q < 8; q++) {
            float4 eA = *reinterpret_cast<const float4*>(&s_ef[warp][0][q * 4]);
            float4 eB = *reinterpret_cast<const float4*>(&s_ef[warp][1][q * 4]);
            float2 w0 = sWc1p[(q * 4 + 0) * 32 + lane];
            float2 w1 = sWc1p[(q * 4 + 1) * 32 + lane];
            float2 w2 = sWc1p[(q * 4 + 2) * 32 + lane];
            float2 w3 = sWc1p[(q * 4 + 3) * 32 + lane];
            t0A = fmaf(eA.x, w0.x, t0A); t1A = fmaf(eA.x, w0.y, t1A);
            t0B = fmaf(eB.x, w0.x, t0B); t1B = fmaf(eB.x, w0.y, t1B);
            t0A = fmaf(eA.y, w1.x, t0A); t1A = fmaf(eA.y, w1.y, t1A);
            t0B = fmaf(eB.y, w1.x, t0B); t1B = fmaf(eB.y, w1.y, t1B);
            t0A = fmaf(eA.z, w2.x, t0A); t1A = fmaf(eA.z, w2.y, t1A);
            t0B = fmaf(eB.z, w2.x, t0B); t1B = fmaf(eB.z, w2.y, t1B);
            t0A = fmaf(eA.w, w3.x, t0A); t1A = fmaf(eA.w, w3.y, t1A);
            t0B = fmaf(eB.w, w3.x, t0B); t1B = fmaf(eB.w, w3.y, t1B);
        }
        t0A = fmaxf(t0A, 0.f); t1A = fmaxf(t1A, 0.f);
        t0B = fmaxf(t0B, 0.f); t1B = fmaxf(t1B, 0.f);
        float wc2a = sWc2[lane], wc2b = sWc2[32 + lane];
        float pA = fmaf(t0A, wc2a, t1A * wc2b);
        float pB = fmaf(t0B, wc2a, t1B * wc2b);
#pragma unroll
        for (int off = 16; off; off >>= 1) {
            pA += __shfl_xor_sync(FULL, pA, off);
            pB += __shfl_xor_sync(FULL, pB, off);
        }

        atomicAdd(&g_sum_ef[row0 * 32 + lane], acc0);
        if (vB) atomicAdd(&g_sum_ef[row1 * 32 + lane], acc1);
        if (lane < 3) {
            float cdA = g_scd[(size_t)jA * 4 + lane];
            atomicAdd(&g_sum_tr[row0 * 3 + lane], cdA * pA);
            if (vB) {
                float cdB = g_scd[(size_t)jB * 4 + lane];
                atomicAdd(&g_sum_tr[row1 * 3 + lane], cdB * pB);
            }
        }
        __syncwarp();
    }
}

// ---------------- node epilogue ----------------
__global__ void node_kernel(const float* __restrict__ h, const float* __restrict__ coord,
                            const float* __restrict__ root, const float* __restrict__ bias,
                            float* __restrict__ out, int N) {
    int warp = threadIdx.x >> 5, lane = threadIdx.x & 31;
    int n = blockIdx.x * 8 + warp;
    if (n >= N) return;
    float hv = h[n * 32 + lane];
    float inv = 1.f / fmaxf((float)g_cnt[n], 1.f);
    float agg = g_sum_ef[n * 32 + lane] * inv + bias[lane];
#pragma unroll
    for (int i = 0; i < 32; i++)
        agg = fmaf(__shfl_sync(0xffffffffu, hv, i), root[i * 32 + lane], agg);
    out[n * 32 + lane] = hv + fmaxf(agg, 0.f) * 0.25f;
    if (lane < 3)
        out[N * 32 + n * 3 + lane] = g_sum_tr[n * 3 + lane] * inv * 0.25f + coord[n * 3 + lane];
}

extern "C" void kernel_launch(void* const* d_in, const int* in_sizes, int n_in,
                              void* d_out, int out_size) {
    const float* h     = (const float*)d_in[0];
    const int*   ei    = (const int*)  d_in[1];
    const float* coord = (const float*)d_in[2];
    const float* ea    = (const float*)d_in[3];
    const float* Wk1   = (const float*)d_in[4];
    const float* bk1   = (const float*)d_in[5];
    const float* Wk2   = (const float*)d_in[6];
    const float* bk2   = (const float*)d_in[7];
    const float* root  = (const float*)d_in[8];
    const float* bias  = (const float*)d_in[9];
    const float* Wc1   = (const float*)d_in[10];
    const float* bc1   = (const float*)d_in[11];
    const float* Wc2   = (const float*)d_in[12];

    int N = in_sizes[0] / 32;
    int E = in_sizes[1] / 2;
    float* out = (float*)d_out;

    zero_kernel<<<(N + 255) / 256, 256>>>(N);
    bperm_kernel<<<(4096 * 32 + 255) / 256, 256>>>(Wk2);
    hb_kernel<<<(N + 7) / 8, 256>>>(h, bk2, N);
    dim3 gg((N + 63) / 64, 8);
    g_kernel<<<gg, 256>>>(h, N);
    hist_kernel<<<(E + 255) / 256, 256>>>(ei, E);
    scan_kernel<<<1, 1024>>>(N);
    scatter_kernel<<<(E + 255) / 256, 256>>>(ei, ea, coord, E);
    edge_kernel<<<592, 256>>>(Wk1, bk1, Wc1, bc1, Wc2, E);
    node_kernel<<<(N + 7) / 8, 256>>>(h, coord, root, bias, out, N);
}

// round 17
// speedup vs baseline: 1.2496x; 1.0969x over previous
#include <cuda_runtime.h>
#include <cuda_bf16.h>
#include <cstdint>

#define NN 10240
#define EE 160000

// Scratch (static device globals)
__device__ __nv_bfloat16 g_G[(size_t)NN * 4096];   // G[n][kb][o][ki]: kb=k/8 (16), o (32), ki=k%8 (8)
__device__ float g_hb[NN * 32];
__device__ float g_Bperm[4096 * 32];
__device__ float g_sum_ef[NN * 32];
__device__ float g_sum_tr[NN * 3];
__device__ int   g_cnt[NN];        // row-degree (mean)
__device__ int   g_deg[NN];        // col-degree (sort)
__device__ int   g_cur[NN];
// sorted edge data (by col)
__device__ int   g_srow[EE];
__device__ int   g_scol[EE];
__device__ float g_sea[(size_t)EE * 8];
__device__ float g_scd[(size_t)EE * 4];

// ---------------- zero (degree arrays only; sums zeroed in hb_kernel) ----------------
__global__ void zero_kernel(int N) {
    int i = blockIdx.x * blockDim.x + threadIdx.x;
    if (i < N) { g_cnt[i] = 0; g_deg[i] = 0; }
}

// ---------------- permute Wk2 for the [kb][o][ki] G layout ----------------
__global__ void bperm_kernel(const float* __restrict__ Wk2) {
    int idx = blockIdx.x * blockDim.x + threadIdx.x;
    if (idx >= 4096 * 32) return;
    int i = idx & 31;
    int c = idx >> 5;
    int kb = c >> 8;
    int o  = (c >> 3) & 31;
    int ki = c & 7;
    int k  = kb * 8 + ki;
    g_Bperm[idx] = Wk2[k * 1024 + i * 32 + o];
}

// ---------------- hb = h @ bk2 ; also zeroes the edge accumulators ----------------
__global__ void hb_kernel(const float* __restrict__ h, const float* __restrict__ bk2, int N) {
    int warp = threadIdx.x >> 5, lane = threadIdx.x & 31;
    int n = blockIdx.x * 8 + warp;
    if (n >= N) return;
    float hv = h[n * 32 + lane];
    float acc = 0.f;
#pragma unroll
    for (int i = 0; i < 32; i++)
        acc = fmaf(__shfl_sync(0xffffffffu, hv, i), bk2[i * 32 + lane], acc);
    g_hb[n * 32 + lane] = acc;
    g_sum_ef[n * 32 + lane] = 0.f;
    if (lane < 3) g_sum_tr[n * 3 + lane] = 0.f;
}

// ---------------- G = H @ Bperm, bf16, 2 cols/thread (R5/R9/R13 proven) ----------------
__global__ __launch_bounds__(256) void g_kernel(const float* __restrict__ h, int N) {
    __shared__ float hs[64 * 32];
    int n0 = blockIdx.x * 64;
    int c0 = (blockIdx.y * 256 + threadIdx.x) * 2;
    int lim = N * 32;
    for (int t = threadIdx.x; t < 64 * 32; t += 256) {
        int gi = n0 * 32 + t;
        hs[t] = (gi < lim) ? h[gi] : 0.f;
    }
    __syncthreads();
    float b0[32], b1[32];
#pragma unroll
    for (int q = 0; q < 8; q++) {
        float4 v0 = *reinterpret_cast<const float4*>(&g_Bperm[(size_t)c0 * 32 + q * 4]);
        float4 v1 = *reinterpret_cast<const float4*>(&g_Bperm[(size_t)(c0 + 1) * 32 + q * 4]);
        b0[q*4+0] = v0.x; b0[q*4+1] = v0.y; b0[q*4+2] = v0.z; b0[q*4+3] = v0.w;
        b1[q*4+0] = v1.x; b1[q*4+1] = v1.y; b1[q*4+2] = v1.z; b1[q*4+3] = v1.w;
    }
    int nmax = min(64, N - n0);
    for (int nn = 0; nn < nmax; nn++) {
        float a0 = 0.f, a1 = 0.f;
#pragma unroll
        for (int q = 0; q < 8; q++) {
            float4 hv = *reinterpret_cast<const float4*>(&hs[nn * 32 + q * 4]);
            a0 = fmaf(hv.x, b0[q*4+0], a0); a1 = fmaf(hv.x, b1[q*4+0], a1);
            a0 = fmaf(hv.y, b0[q*4+1], a0); a1 = fmaf(hv.y, b1[q*4+1], a1);
            a0 = fmaf(hv.z, b0[q*4+2], a0); a1 = fmaf(hv.z, b1[q*4+2], a1);
            a0 = fmaf(hv.w, b0[q*4+3], a0); a1 = fmaf(hv.w, b1[q*4+3], a1);
        }
        *reinterpret_cast<__nv_bfloat162*>(&g_G[(size_t)(n0 + nn) * 4096 + c0]) =
            __floats2bfloat162_rn(a0, a1);
    }
}

// ---------------- histograms ----------------
__global__ void hist_kernel(const int* __restrict__ ei, int E) {
    int e = blockIdx.x * blockDim.x + threadIdx.x;
    if (e >= E) return;
    atomicAdd(&g_deg[ei[E + e]], 1);
    atomicAdd(&g_cnt[ei[e]], 1);
}

// ---------------- exclusive scan of col-degrees ----------------
__global__ void scan_kernel(int N) {
    __shared__ int s[1024];
    int tid = threadIdx.x;
    int base = tid * 10;
    int local[10];
    int sum = 0;
#pragma unroll
    for (int i = 0; i < 10; i++) {
        int idx = base + i;
        int v = (idx < N) ? g_deg[idx] : 0;
        local[i] = sum; sum += v;
    }
    s[tid] = sum;
    __syncthreads();
    for (int off = 1; off < 1024; off <<= 1) {
        int v = (tid >= off) ? s[tid - off] : 0;
        __syncthreads();
        s[tid] += v;
        __syncthreads();
    }
    int pre = (tid > 0) ? s[tid - 1] : 0;
#pragma unroll
    for (int i = 0; i < 10; i++) {
        int idx = base + i;
        if (idx < N) g_cur[idx] = pre + local[i];
    }
}

// ---------------- scatter: build fully sorted edge records ----------------
__global__ void scatter_kernel(const int* __restrict__ ei, const float* __restrict__ ea,
                               const float* __restrict__ coord, int E) {
    int e = blockIdx.x * blockDim.x + threadIdx.x;
    if (e >= E) return;
    int row = ei[e];
    int col = ei[E + e];
    int pos = atomicAdd(&g_cur[col], 1);
    g_srow[pos] = row;
    g_scol[pos] = col;
    float a0 = ea[e * 6 + 0], a1 = ea[e * 6 + 1], a2 = ea[e * 6 + 2];
    float a3 = ea[e * 6 + 3], a4 = ea[e * 6 + 4], a5 = ea[e * 6 + 5];
    float4* sp = reinterpret_cast<float4*>(&g_sea[(size_t)pos * 8]);
    sp[0] = make_float4(a0, a1, a2, a3);
    sp[1] = make_float4(a4, a5, 0.f, 0.f);
    float c0 = coord[row * 3 + 0] - coord[col * 3 + 0];
    float c1 = coord[row * 3 + 1] - coord[col * 3 + 1];
    float c2 = coord[row * 3 + 2] - coord[col * 3 + 2];
    *reinterpret_cast<float4*>(&g_scd[(size_t)pos * 4]) = make_float4(c0, c1, c2, 0.f);
}

// ---------------- edge kernel: 2 edges/warp-iter, col-dedup gather (R13 proven) ----------------
__global__ __launch_bounds__(256) void edge_kernel(
        const float* __restrict__ Wk1, const float* __restrict__ bk1,
        const float* __restrict__ Wc1, const float* __restrict__ bc1,
        const float* __restrict__ Wc2, int E) {
    __shared__ float sWk1[768], sbk1[128], sbc1[64], sWc2[64];
    __shared__ float2 sWc1p[1024];
    __shared__ float s_rz[8][2][128];
    __shared__ __align__(16) float s_ef[8][2][32];
    int tid = threadIdx.x;
    for (int t = tid; t < 768; t += 256)  sWk1[t] = Wk1[t];
    for (int t = tid; t < 1024; t += 256) {
        int o = t >> 5, l = t & 31;
        sWc1p[t] = make_float2(Wc1[o * 64 + l], Wc1[o * 64 + 32 + l]);
    }
    if (tid < 128) sbk1[tid] = bk1[tid];
    if (tid < 64)  sbc1[tid] = bc1[tid];
    if (tid < 64)  sWc2[tid] = Wc2[tid];
    __syncthreads();

    int warp = tid >> 5, lane = tid & 31;
    const unsigned FULL = 0xffffffffu;
    int per = (E + gridDim.x - 1) / gridDim.x;
    int j0 = blockIdx.x * per;
    int j1 = min(j0 + per, E);

    for (int j = j0 + warp * 2; j < j1; j += 16) {
        int jA = j;
        int jB = j + 1;
        bool vB = jB < j1;
        int row0 = g_srow[jA], col0 = g_scol[jA];
        int row1 = vB ? g_srow[jB] : row0;
        int col1 = vB ? g_scol[jB] : col0;

        float eaA = (lane < 6) ? g_sea[(size_t)jA * 8 + lane] : 0.f;
        float eaB = (vB && lane < 6) ? g_sea[(size_t)jB * 8 + lane] : 0.f;
        float a0A = __shfl_sync(FULL, eaA, 0), a1A = __shfl_sync(FULL, eaA, 1);
        float a2A = __shfl_sync(FULL, eaA, 2), a3A = __shfl_sync(FULL, eaA, 3);
        float a4A = __shfl_sync(FULL, eaA, 4), a5A = __shfl_sync(FULL, eaA, 5);
        float a0B = __shfl_sync(FULL, eaB, 0), a1B = __shfl_sync(FULL, eaB, 1);
        float a2B = __shfl_sync(FULL, eaB, 2), a3B = __shfl_sync(FULL, eaB, 3);
        float a4B = __shfl_sync(FULL, eaB, 4), a5B = __shfl_sync(FULL, eaB, 5);

        // rz = relu(ea @ Wk1 + bk1) for both edges; weight LDS shared
#pragma unroll
        for (int r = 0; r < 4; r++) {
            int k = r * 32 + lane;
            float w0 = sWk1[k], w1 = sWk1[128 + k], w2 = sWk1[256 + k];
            float w3 = sWk1[384 + k], w4 = sWk1[512 + k], w5 = sWk1[640 + k];
            float b = sbk1[k];
            float vA = b, vBv = b;
            vA = fmaf(a0A, w0, vA); vBv = fmaf(a0B, w0, vBv);
            vA = fmaf(a1A, w1, vA); vBv = fmaf(a1B, w1, vBv);
            vA = fmaf(a2A, w2, vA); vBv = fmaf(a2B, w2, vBv);
            vA = fmaf(a3A, w3, vA); vBv = fmaf(a3B, w3, vBv);
            vA = fmaf(a4A, w4, vA); vBv = fmaf(a4B, w4, vBv);
            vA = fmaf(a5A, w5, vA); vBv = fmaf(a5B, w5, vBv);
            s_rz[warp][0][k] = fmaxf(vA, 0.f);
            s_rz[warp][1][k] = fmaxf(vBv, 0.f);
        }
        __syncwarp();

        // ef = hb[col] + rz . G[col]; sorted pairs share col ~94% -> dedup branch
        float acc0 = g_hb[col0 * 32 + lane];
        float acc1;
        const __nv_bfloat16* gp0 = g_G + (size_t)col0 * 4096 + lane * 8;
        if (col1 == col0) {
            acc1 = acc0;
#pragma unroll
            for (int kc = 0; kc < 16; kc++) {
                uint4 gv = *reinterpret_cast<const uint4*>(gp0 + kc * 256);
                float4 ra0 = *reinterpret_cast<const float4*>(&s_rz[warp][0][kc * 8]);
                float4 rb0 = *reinterpret_cast<const float4*>(&s_rz[warp][0][kc * 8 + 4]);
                float4 ra1 = *reinterpret_cast<const float4*>(&s_rz[warp][1][kc * 8]);
                float4 rb1 = *reinterpret_cast<const float4*>(&s_rz[warp][1][kc * 8 + 4]);
                float2 f0 = __bfloat1622float2(*reinterpret_cast<const __nv_bfloat162*>(&gv.x));
                float2 f1 = __bfloat1622float2(*reinterpret_cast<const __nv_bfloat162*>(&gv.y));
                float2 f2 = __bfloat1622float2(*reinterpret_cast<const __nv_bfloat162*>(&gv.z));
                float2 f3 = __bfloat1622float2(*reinterpret_cast<const __nv_bfloat162*>(&gv.w));
                acc0 = fmaf(ra0.x, f0.x, acc0); acc1 = fmaf(ra1.x, f0.x, acc1);
                acc0 = fmaf(ra0.y, f0.y, acc0); acc1 = fmaf(ra1.y, f0.y, acc1);
                acc0 = fmaf(ra0.z, f1.x, acc0); acc1 = fmaf(ra1.z, f1.x, acc1);
                acc0 = fmaf(ra0.w, f1.y, acc0); acc1 = fmaf(ra1.w, f1.y, acc1);
                acc0 = fmaf(rb0.x, f2.x, acc0); acc1 = fmaf(rb1.x, f2.x, acc1);
                acc0 = fmaf(rb0.y, f2.y, acc0); acc1 = fmaf(rb1.y, f2.y, acc1);
                acc0 = fmaf(rb0.z, f3.x, acc0); acc1 = fmaf(rb1.z, f3.x, acc1);
                acc0 = fmaf(rb0.w, f3.y, acc0); acc1 = fmaf(rb1.w, f3.y, acc1);
            }
        } else {
            const __nv_bfloat16* gp1 = g_G + (size_t)col1 * 4096 + lane * 8;
            acc1 = g_hb[col1 * 32 + lane];
#pragma unroll
            for (int kc = 0; kc < 16; kc++) {
                uint4 gv0 = *reinterpret_cast<const uint4*>(gp0 + kc * 256);
                uint4 gv1 = *reinterpret_cast<const uint4*>(gp1 + kc * 256);
                float4 ra0 = *reinterpret_cast<const float4*>(&s_rz[warp][0][kc * 8]);
                float4 rb0 = *reinterpret_cast<const float4*>(&s_rz[warp][0][kc * 8 + 4]);
                float4 ra1 = *reinterpret_cast<const float4*>(&s_rz[warp][1][kc * 8]);
                float4 rb1 = *reinterpret_cast<const float4*>(&s_rz[warp][1][kc * 8 + 4]);
                float2 f;
                f = __bfloat1622float2(*reinterpret_cast<const __nv_bfloat162*>(&gv0.x));
                acc0 = fmaf(ra0.x, f.x, acc0); acc0 = fmaf(ra0.y, f.y, acc0);
                f = __bfloat1622float2(*reinterpret_cast<const __nv_bfloat162*>(&gv0.y));
                acc0 = fmaf(ra0.z, f.x, acc0); acc0 = fmaf(ra0.w, f.y, acc0);
                f = __bfloat1622float2(*reinterpret_cast<const __nv_bfloat162*>(&gv0.z));
                acc0 = fmaf(rb0.x, f.x, acc0); acc0 = fmaf(rb0.y, f.y, acc0);
                f = __bfloat1622float2(*reinterpret_cast<const __nv_bfloat162*>(&gv0.w));
                acc0 = fmaf(rb0.z, f.x, acc0); acc0 = fmaf(rb0.w, f.y, acc0);
                f = __bfloat1622float2(*reinterpret_cast<const __nv_bfloat162*>(&gv1.x));
                acc1 = fmaf(ra1.x, f.x, acc1); acc1 = fmaf(ra1.y, f.y, acc1);
                f = __bfloat1622float2(*reinterpret_cast<const __nv_bfloat162*>(&gv1.y));
                acc1 = fmaf(ra1.z, f.x, acc1); acc1 = fmaf(ra1.w, f.y, acc1);
                f = __bfloat1622float2(*reinterpret_cast<const __nv_bfloat162*>(&gv1.z));
                acc1 = fmaf(rb1.x, f.x, acc1); acc1 = fmaf(rb1.y, f.y, acc1);
                f = __bfloat1622float2(*reinterpret_cast<const __nv_bfloat162*>(&gv1.w));
                acc1 = fmaf(rb1.z, f.x, acc1); acc1 = fmaf(rb1.w, f.y, acc1);
            }
        }

        // stash ef to smem; read back as float4 broadcasts for the coord MLP
        s_ef[warp][0][lane] = acc0;
        s_ef[warp][1][lane] = acc1;
        __syncwarp();

        float t0A = sbc1[lane], t1A = sbc1[32 + lane];
        float t0B = t0A, t1B = t1A;
#pragma unroll
        for (int q = 0; q < 8; q++) {
            float4 eA = *reinterpret_cast<const float4*>(&s_ef[warp][0][q * 4]);
            float4 eB = *reinterpret_cast<const float4*>(&s_ef[warp][1][q * 4]);
            float2 w0 = sWc1p[(q * 4 + 0) * 32 + lane];
            float2 w1 = sWc1p[(q * 4 + 1) * 32 + lane];
            float2 w2 = sWc1p[(q * 4 + 2) * 32 + lane];
            float2 w3 = sWc1p[(q * 4 + 3) * 32 + lane];
            t0A = fmaf(eA.x, w0.x, t0A); t1A = fmaf(eA.x, w0.y, t1A);
            t0B = fmaf(eB.x, w0.x, t0B); t1B = fmaf(eB.x, w0.y, t1B);
            t0A = fmaf(eA.y, w1.x, t0A); t1A = fmaf(eA.y, w1.y, t1A);
            t0B = fmaf(eB.y, w1.x, t0B); t1B = fmaf(eB.y, w1.y, t1B);
            t0A = fmaf(eA.z, w2.x, t0A); t1A = fmaf(eA.z, w2.y, t1A);
            t0B = fmaf(eB.z, w2.x, t0B); t1B = fmaf(eB.z, w2.y, t1B);
            t0A = fmaf(eA.w, w3.x, t0A); t1A = fmaf(eA.w, w3.y, t1A);
            t0B = fmaf(eB.w, w3.x, t0B); t1B = fmaf(eB.w, w3.y, t1B);
        }
        t0A = fmaxf(t0A, 0.f); t1A = fmaxf(t1A, 0.f);
        t0B = fmaxf(t0B, 0.f); t1B = fmaxf(t1B, 0.f);
        float wc2a = sWc2[lane], wc2b = sWc2[32 + lane];
        float pA = fmaf(t0A, wc2a, t1A * wc2b);
        float pB = fmaf(t0B, wc2a, t1B * wc2b);
#pragma unroll
        for (int off = 16; off; off >>= 1) {
            pA += __shfl_xor_sync(FULL, pA, off);
            pB += __shfl_xor_sync(FULL, pB, off);
        }

        atomicAdd(&g_sum_ef[row0 * 32 + lane], acc0);
        if (vB) atomicAdd(&g_sum_ef[row1 * 32 + lane], acc1);
        if (lane < 3) {
            float cdA = g_scd[(size_t)jA * 4 + lane];
            atomicAdd(&g_sum_tr[row0 * 3 + lane], cdA * pA);
            if (vB) {
                float cdB = g_scd[(size_t)jB * 4 + lane];
                atomicAdd(&g_sum_tr[row1 * 3 + lane], cdB * pB);
            }
        }
        __syncwarp();
    }
}

// ---------------- node epilogue ----------------
__global__ void node_kernel(const float* __restrict__ h, const float* __restrict__ coord,
                            const float* __restrict__ root, const float* __restrict__ bias,
                            float* __restrict__ out, int N) {
    int warp = threadIdx.x >> 5, lane = threadIdx.x & 31;
    int n = blockIdx.x * 8 + warp;
    if (n >= N) return;
    float hv = h[n * 32 + lane];
    float inv = 1.f / fmaxf((float)g_cnt[n], 1.f);
    float agg = g_sum_ef[n * 32 + lane] * inv + bias[lane];
#pragma unroll
    for (int i = 0; i < 32; i++)
        agg = fmaf(__shfl_sync(0xffffffffu, hv, i), root[i * 32 + lane], agg);
    out[n * 32 + lane] = hv + fmaxf(agg, 0.f) * 0.25f;
    if (lane < 3)
        out[N * 32 + n * 3 + lane] = g_sum_tr[n * 3 + lane] * inv * 0.25f + coord[n * 3 + lane];
}

extern "C" void kernel_launch(void* const* d_in, const int* in_sizes, int n_in,
                              void* d_out, int out_size) {
    const float* h     = (const float*)d_in[0];
    const int*   ei    = (const int*)  d_in[1];
    const float* coord = (const float*)d_in[2];
    const float* ea    = (const float*)d_in[3];
    const float* Wk1   = (const float*)d_in[4];
    const float* bk1   = (const float*)d_in[5];
    const float* Wk2   = (const float*)d_in[6];
    const float* bk2   = (const float*)d_in[7];
    const float* root  = (const float*)d_in[8];
    const float* bias  = (const float*)d_in[9];
    const float* Wc1   = (const float*)d_in[10];
    const float* bc1   = (const float*)d_in[11];
    const float* Wc2   = (const float*)d_in[12];

    int N = in_sizes[0] / 32;
    int E = in_sizes[1] / 2;
    float* out = (float*)d_out;

    zero_kernel<<<(N + 255) / 256, 256>>>(N);
    bperm_kernel<<<(4096 * 32 + 255) / 256, 256>>>(Wk2);
    hb_kernel<<<(N + 7) / 8, 256>>>(h, bk2, N);
    dim3 gg((N + 63) / 64, 8);
    g_kernel<<<gg, 256>>>(h, N);
    hist_kernel<<<(E + 255) / 256, 256>>>(ei, E);
    scan_kernel<<<1, 1024>>>(N);
    scatter_kernel<<<(E + 255) / 256, 256>>>(ei, ea, coord, E);
    edge_kernel<<<592, 256>>>(Wk1, bk1, Wc1, bc1, Wc2, E);
    node_kernel<<<(N + 7) / 8, 256>>>(h, coord, root, bias, out, N);
}